// round 11
// baseline (speedup 1.0000x reference)
#include <cuda_runtime.h>
#include <cstdint>

#define H     50
#define E     4
#define KPAD  64
#define BSZ   512
#define NTH   448
#define NSLOT 9            // 8 k-partials + 1 bias slot

// dynamic smem layout
#define OFF_H1 0
#define OFF_H2 1024
#define OFF_P1 2048
#define OFF_P2 (2048 + 28800)
#define OFF_OB (2048 + 2 * 28800)
#define OFF_OS (OFF_OB + 832)
#define SMEM_BYTES (OFF_OS + 32)

typedef unsigned long long u64;

__device__ __forceinline__ void fma2(u64 &d, u64 a, u64 b) {
    asm("fma.rn.f32x2 %0, %1, %2, %0;" : "+l"(d) : "l"(a), "l"(b));
}
__device__ __forceinline__ u64 padd(u64 a, u64 b) {
    u64 d; asm("add.rn.f32x2 %0, %1, %2;" : "=l"(d) : "l"(a), "l"(b)); return d;
}
__device__ __forceinline__ float lo32(u64 a){ return __uint_as_float((unsigned)a); }
__device__ __forceinline__ float hi32(u64 a){ return __uint_as_float((unsigned)(a >> 32)); }
__device__ __forceinline__ float hsum2(u64 a){ return lo32(a) + hi32(a); }
__device__ __forceinline__ u64 pk2(float lo, float hi) {
    return ((u64)__float_as_uint(hi) << 32) | (u64)__float_as_uint(lo);
}
__device__ __forceinline__ float sigf(float v) {
    return __fdividef(1.0f, 1.0f + __expf(-v));
}
__device__ __forceinline__ float tanhf_(float v) {
    return 1.0f - __fdividef(2.0f, 1.0f + __expf(2.0f * v));
}

// 4-row dot over this lane's 8 h-floats, one weight set (2 LDS.128, 16 FFMA2)
__device__ __forceinline__ void dot4(const float* __restrict__ hb, const u64 (&w)[4][4], u64 (&a)[4]) {
    const ulonglong2* hp = (const ulonglong2*)hb;
    ulonglong2 hA = hp[0], hB = hp[1];
    #pragma unroll
    for (int r = 0; r < 4; r++) {
        fma2(a[r], w[r][0], hA.x);
        fma2(a[r], w[r][1], hA.y);
        fma2(a[r], w[r][2], hB.x);
        fma2(a[r], w[r][3], hB.y);
    }
}
// same h reused for two weight sets (2 LDS.128, 32 FFMA2)
__device__ __forceinline__ void dot4x2(const float* __restrict__ hb,
                                       const u64 (&wA)[4][4], const u64 (&wB)[4][4],
                                       u64 (&a)[4], u64 (&b)[4]) {
    const ulonglong2* hp = (const ulonglong2*)hb;
    ulonglong2 hA = hp[0], hB = hp[1];
    #pragma unroll
    for (int r = 0; r < 4; r++) {
        fma2(a[r], wA[r][0], hA.x); fma2(a[r], wA[r][1], hA.y);
        fma2(a[r], wA[r][2], hB.x); fma2(a[r], wA[r][3], hB.y);
        fma2(b[r], wB[r][0], hA.x); fma2(b[r], wB[r][1], hA.y);
        fma2(b[r], wB[r][2], hB.x); fma2(b[r], wB[r][3], hB.y);
    }
}

__global__ void __launch_bounds__(NTH, 1) sinelstm_kernel(
    const float* __restrict__ x,
    const float* __restrict__ W_ih1, const float* __restrict__ W_hh1,
    const float* __restrict__ b_ih1, const float* __restrict__ b_hh1,
    const float* __restrict__ W_ih2, const float* __restrict__ W_hh2,
    const float* __restrict__ b_ih2, const float* __restrict__ b_hh2,
    const float* __restrict__ W_lin, const float* __restrict__ b_lin,
    float* __restrict__ out, int T, int TP)
{
    extern __shared__ __align__(16) char smem_raw[];
    float  (*h1s)[KPAD]     = (float  (*)[KPAD])    (smem_raw + OFF_H1);
    float  (*h2s)[KPAD]     = (float  (*)[KPAD])    (smem_raw + OFF_H2);
    float4 (*p1)[H][NSLOT]  = (float4 (*)[H][NSLOT])(smem_raw + OFF_P1);
    float4 (*p2)[H][NSLOT]  = (float4 (*)[H][NSLOT])(smem_raw + OFF_P2);
    float  (*obuf)[52]      = (float  (*)[52])      (smem_raw + OFF_OB);
    float  *outs_s          = (float  *)            (smem_raw + OFF_OS);

    const int  t     = threadIdx.x;
    const int  base  = blockIdx.x * E;
    const bool dotth = (t < 400);
    const int  u     = t >> 3;          // unit (dot role)
    const int  k     = t & 7;           // k-lane

    // act roles: t<200 -> layer1 (e,u); 200<=t<400 -> layer2
    const bool l1t = (t < 200);
    const bool l2t = (t >= 200) && (t < 400);
    const int  ui  = t % 200;
    const int  ue  = ui / 50;
    const int  uu  = ui % 50;

    const bool fin = (t >= 440) && (t < 444);
    const int  fe  = t - 440;

    // ---- register-resident weights: 4 gate rows of unit u, cols [8k, 8k+8) ----
    u64 w1[4][4], wa[4][4], wb[4][4];
    if (dotth) {
        #pragma unroll
        for (int rr = 0; rr < 4; rr++) {
            const int row = rr * H + u;     // i,f,g,o rows
            #pragma unroll
            for (int p = 0; p < 4; p++) {
                const int col = k * 8 + 2 * p;
                float a0 = (col     < H) ? W_hh1[row * H + col]     : 0.f;
                float a1 = (col + 1 < H) ? W_hh1[row * H + col + 1] : 0.f;
                w1[rr][p] = pk2(a0, a1);
                float c0 = (col     < H) ? W_ih2[row * H + col]     : 0.f;
                float c1v= (col + 1 < H) ? W_ih2[row * H + col + 1] : 0.f;
                wa[rr][p] = pk2(c0, c1v);
                float d0 = (col     < H) ? W_hh2[row * H + col]     : 0.f;
                float d1 = (col + 1 < H) ? W_hh2[row * H + col + 1] : 0.f;
                wb[rr][p] = pk2(d0, d1);
            }
        }
    }

    // act-role constants
    u64 wx_if = 0ull, wx_go = 0ull;
    float wlin_u = 0.f;
    if (l1t) {
        wx_if = pk2(W_ih1[uu], W_ih1[uu + H]);
        wx_go = pk2(W_ih1[uu + 2 * H], W_ih1[uu + 3 * H]);
    }
    if (l2t) wlin_u = __ldg(&W_lin[uu]);
    const float blin = b_lin[0];
    float cst = 0.f;                     // c1 (l1t) or c2 (l2t)

    // ---- init shared state ----
    for (int i = t; i < E * KPAD; i += NTH) { ((float*)h1s)[i] = 0.f; ((float*)h2s)[i] = 0.f; }
    for (int i = t; i < E * 52;   i += NTH) ((float*)obuf)[i] = 0.f;
    if (t < 200) {                       // bias slots (persist; dots only rewrite slots 0-7)
        const int e = t / 50, un = t % 50;
        float4 bb;
        bb.x = b_ih1[un] + b_hh1[un];
        bb.y = b_ih1[un + H] + b_hh1[un + H];
        bb.z = b_ih1[un + 2 * H] + b_hh1[un + 2 * H];
        bb.w = b_ih1[un + 3 * H] + b_hh1[un + 3 * H];
        p1[e][un][8] = bb;
        bb.x = b_ih2[un] + b_hh2[un];
        bb.y = b_ih2[un + H] + b_hh2[un + H];
        bb.z = b_ih2[un + 2 * H] + b_hh2[un + 2 * H];
        bb.w = b_ih2[un + 3 * H] + b_hh2[un + 3 * H];
        p2[e][un][8] = bb;
    }
    __syncthreads();

    // ---- lambdas ----
    auto dots_g1 = [&]() {               // W_hh1*h1 -> p1
        #pragma unroll
        for (int e = 0; e < E; e++) {
            u64 a[4] = {0,0,0,0};
            dot4(&h1s[e][k * 8], w1, a);
            p1[e][u][k] = make_float4(hsum2(a[0]), hsum2(a[1]), hsum2(a[2]), hsum2(a[3]));
        }
    };
    auto dots_g2 = [&]() {               // W_ih2*h1 + W_hh2*h2 -> p2
        #pragma unroll
        for (int e = 0; e < E; e++) {
            u64 b[4] = {0,0,0,0}, c[4] = {0,0,0,0};
            dot4(&h1s[e][k * 8], wa, b);
            dot4(&h2s[e][k * 8], wb, c);
            #pragma unroll
            for (int r = 0; r < 4; r++) b[r] = padd(b[r], c[r]);
            p2[e][u][k] = make_float4(hsum2(b[0]), hsum2(b[1]), hsum2(b[2]), hsum2(b[3]));
        }
    };
    auto dots_all = [&](bool wr2) {      // fused: g1(s) + g2(s-1), h1 loads shared
        #pragma unroll
        for (int e = 0; e < E; e++) {
            u64 a[4] = {0,0,0,0}, b[4] = {0,0,0,0}, c[4] = {0,0,0,0};
            dot4x2(&h1s[e][k * 8], w1, wa, a, b);
            dot4  (&h2s[e][k * 8], wb, c);
            p1[e][u][k] = make_float4(hsum2(a[0]), hsum2(a[1]), hsum2(a[2]), hsum2(a[3]));
            if (wr2) {
                #pragma unroll
                for (int r = 0; r < 4; r++) b[r] = padd(b[r], c[r]);
                p2[e][u][k] = make_float4(hsum2(b[0]), hsum2(b[1]), hsum2(b[2]), hsum2(b[3]));
            }
        }
    };
    auto act1 = [&](float xv) {          // pre-gates from p1 (+bias slot) + x-term
        const ulonglong2* pp = (const ulonglong2*)&p1[ue][uu][0];
        ulonglong2 acc = pp[0];
        #pragma unroll
        for (int q = 1; q < 9; q++) { ulonglong2 v = pp[q]; acc.x = padd(acc.x, v.x); acc.y = padd(acc.y, v.y); }
        u64 xv2 = pk2(xv, xv);
        fma2(acc.x, wx_if, xv2);
        fma2(acc.y, wx_go, xv2);
        float gi = lo32(acc.x), gf = hi32(acc.x), gg = lo32(acc.y), go = hi32(acc.y);
        cst = sigf(gf) * cst + sigf(gi) * tanhf_(gg);
        h1s[ue][uu] = sigf(go) * tanhf_(cst);
    };
    auto act2 = [&]() {
        const ulonglong2* pp = (const ulonglong2*)&p2[ue][uu][0];
        ulonglong2 acc = pp[0];
        #pragma unroll
        for (int q = 1; q < 9; q++) { ulonglong2 v = pp[q]; acc.x = padd(acc.x, v.x); acc.y = padd(acc.y, v.y); }
        float gi = lo32(acc.x), gf = hi32(acc.x), gg = lo32(acc.y), go = hi32(acc.y);
        cst = sigf(gf) * cst + sigf(gi) * tanhf_(gg);
        float h2 = sigf(go) * tanhf_(cst);
        h2s[ue][uu] = h2;
        obuf[ue][uu] = wlin_u * h2;
    };
    auto finalize_out = [&](int ostep, bool seed) {
        if (fin) {
            const float4* ob = (const float4*)obuf[fe];
            float a0 = 0.f, a1 = 0.f, a2 = 0.f, a3 = 0.f;
            #pragma unroll
            for (int q = 0; q < 13; q += 4) {
                float4 v0 = ob[q];     a0 += v0.x + v0.y + v0.z + v0.w;
                if (q + 1 < 13) { float4 v1 = ob[q + 1]; a1 += v1.x + v1.y + v1.z + v1.w; }
                if (q + 2 < 13) { float4 v2 = ob[q + 2]; a2 += v2.x + v2.y + v2.z + v2.w; }
                if (q + 3 < 13) { float4 v3 = ob[q + 3]; a3 += v3.x + v3.y + v3.z + v3.w; }
            }
            float o = (a0 + a1) + (a2 + a3) + blin;
            out[(size_t)(base + fe) * TP + ostep] = o;
            if (seed) outs_s[fe] = o;
        }
    };

    // ================= main loop: 2 barriers/step =================
    // iter s: R1 = partials for g1(s) & g2(s-1); finalize out(s-2)
    //         R2 = act1 -> h1(s); act2 -> h2(s-1) + obuf(s-1)
    for (int s = 0; s < T; s++) {
        float xv = 0.f;
        if (l1t) xv = __ldg(&x[(size_t)(base + ue) * T + s]);   // prefetch, used after barrier
        if (dotth) dots_all(s > 0);
        else if (s >= 2) finalize_out(s - 2, false);
        __syncthreads();   // A
        if (l1t) act1(xv);
        else if (l2t && s > 0) act2();
        __syncthreads();   // B
    }

    // ---- epilogue: g2(T-1) -> act2 -> out(T-2), out(T-1), seed feedback ----
    if (dotth) dots_g2();
    else finalize_out(T - 2, false);
    __syncthreads();
    if (l2t) act2();
    __syncthreads();
    finalize_out(T - 1, true);
    __syncthreads();

    // ================= predict loop: strict ordering =================
    for (int s = T; s < TP; s++) {
        if (dotth) dots_g1();
        __syncthreads();
        if (l1t) act1(outs_s[ue]);
        __syncthreads();
        if (dotth) dots_g2();
        __syncthreads();
        if (l2t) act2();
        __syncthreads();
        finalize_out(s, true);
        __syncthreads();
    }
}

extern "C" void kernel_launch(void* const* d_in, const int* in_sizes, int n_in,
                              void* d_out, int out_size) {
    const float* x     = (const float*)d_in[0];
    const float* W_ih1 = (const float*)d_in[1];
    const float* W_hh1 = (const float*)d_in[2];
    const float* b_ih1 = (const float*)d_in[3];
    const float* b_hh1 = (const float*)d_in[4];
    const float* W_ih2 = (const float*)d_in[5];
    const float* W_hh2 = (const float*)d_in[6];
    const float* b_ih2 = (const float*)d_in[7];
    const float* b_hh2 = (const float*)d_in[8];
    const float* W_lin = (const float*)d_in[9];
    const float* b_lin = (const float*)d_in[10];

    int T  = in_sizes[0] / BSZ;      // 1024
    int TP = out_size   / BSZ;       // 1056

    cudaFuncSetAttribute(sinelstm_kernel,
                         cudaFuncAttributeMaxDynamicSharedMemorySize, SMEM_BYTES);
    sinelstm_kernel<<<BSZ / E, NTH, SMEM_BYTES>>>(
        x, W_ih1, W_hh1, b_ih1, b_hh1,
        W_ih2, W_hh2, b_ih2, b_hh2,
        W_lin, b_lin, (float*)d_out, T, TP);
}